// round 2
// baseline (speedup 1.0000x reference)
#include <cuda_runtime.h>
#include <math_constants.h>
#include <cstdint>

// Problem constants (fixed by this problem instance)
#define DIMS    128
#define NQ      2048
#define MBANK   100000
#define KNN     5

// Tiling
#define QT      128      // queries per block tile
#define MT      128      // bank rows per block tile
#define KC      32       // k-chunk
#define NSPLIT  18       // M splits (grid.y)
#define NTHR    512
#define STRIDE  132      // smem row stride in floats (pad 128 -> conflict-free)

#define MS_LEN  ((MBANK + NSPLIT - 1) / NSPLIT)   // 5556 rows per split

// Scratch (static device globals: no allocation allowed)
__device__ float g_y2[MBANK];
__device__ float g_part[(size_t)NQ * NSPLIT * KNN];

// ---------------------------------------------------------------------------
// Kernel 1: y2[m] = ||bank[m]||^2   (warp per row)
// ---------------------------------------------------------------------------
__global__ void y2_kernel(const float* __restrict__ bank) {
    int wid  = threadIdx.x >> 5;
    int lane = threadIdx.x & 31;
    int row  = blockIdx.x * (blockDim.x >> 5) + wid;
    if (row >= MBANK) return;
    const float4* p = reinterpret_cast<const float4*>(bank + (size_t)row * DIMS);
    float4 v = p[lane];                      // DIMS/4 == 32 == warp size
    float s = v.x*v.x + v.y*v.y + v.z*v.z + v.w*v.w;
    #pragma unroll
    for (int o = 16; o; o >>= 1) s += __shfl_xor_sync(0xffffffffu, s, o);
    if (lane == 0) g_y2[row] = s;
}

// ---------------------------------------------------------------------------
// Kernel 2: tiled distance GEMM with fused per-thread top-5
// Block: (qtile, split). 512 threads; thread = (qr = tid/16 in [0,32), mc = tid%16)
// Microtile: 4 query rows (qr*4..+3) x 8 bank cols ({mc*4..+3} U {64+mc*4..+3})
// ---------------------------------------------------------------------------
struct Tiles {
    float A[KC][STRIDE];   // A[k][i] = feat[q0+i][kc+k]
    float B[KC][STRIDE];   // B[k][j] = bank[m0+j][kc+k]
};
union SMem {
    Tiles t;
    float cand[QT][16 * KNN];   // block-level top-5 merge buffer (40 KB)
};

__global__ __launch_bounds__(NTHR, 1)
void knn_main(const float* __restrict__ feat, const float* __restrict__ bank) {
    __shared__ SMem sm;
    __shared__ float ys[MT];

    const int tid = threadIdx.x;
    const int qr  = tid >> 4;          // 0..31
    const int mc  = tid & 15;          // 0..15
    const int q0  = blockIdx.x * QT;
    const int sp  = blockIdx.y;
    const int mBeg = sp * MS_LEN;
    const int mEnd = min(MBANK, mBeg + MS_LEN);

    // per-thread top-5 (smaller key = closer)
    float t5[4][KNN];
    float worst[4];
    #pragma unroll
    for (int r = 0; r < 4; r++) {
        worst[r] = CUDART_INF_F;
        #pragma unroll
        for (int t = 0; t < KNN; t++) t5[r][t] = CUDART_INF_F;
    }

    const int lrow = tid >> 3;            // 0..63 (loader row base)
    const int kq   = (tid & 7) * 4;       // 0,4,...,28 (loader k offset)

    for (int m0 = mBeg; m0 < mEnd; m0 += MT) {
        __syncthreads();   // protect ys + smem from previous iteration's readers
        if (tid < MT) {
            int r = m0 + tid;
            ys[tid] = (r < mEnd) ? g_y2[r] : CUDART_INF_F;
        }

        float acc[4][8];
        #pragma unroll
        for (int r = 0; r < 4; r++)
            #pragma unroll
            for (int c = 0; c < 8; c++) acc[r][c] = 0.f;

        for (int kc = 0; kc < DIMS; kc += KC) {
            if (kc) __syncthreads();   // first chunk covered by loop-top sync
            // Load + transpose A and B chunks (2 passes of 64 rows)
            #pragma unroll
            for (int pass = 0; pass < 2; pass++) {
                int rr = lrow + pass * 64;
                // A: always in range (NQ divisible by QT)
                float4 a = *reinterpret_cast<const float4*>(
                    feat + (size_t)(q0 + rr) * DIMS + kc + kq);
                sm.t.A[kq + 0][rr] = a.x;
                sm.t.A[kq + 1][rr] = a.y;
                sm.t.A[kq + 2][rr] = a.z;
                sm.t.A[kq + 3][rr] = a.w;
                int gr = m0 + rr;
                float4 b = make_float4(0.f, 0.f, 0.f, 0.f);
                if (gr < mEnd)
                    b = *reinterpret_cast<const float4*>(
                        bank + (size_t)gr * DIMS + kc + kq);
                sm.t.B[kq + 0][rr] = b.x;
                sm.t.B[kq + 1][rr] = b.y;
                sm.t.B[kq + 2][rr] = b.z;
                sm.t.B[kq + 3][rr] = b.w;
            }
            __syncthreads();

            #pragma unroll 8
            for (int k = 0; k < KC; k++) {
                float4 a  = *reinterpret_cast<const float4*>(&sm.t.A[k][qr * 4]);
                float4 b0 = *reinterpret_cast<const float4*>(&sm.t.B[k][mc * 4]);
                float4 b1 = *reinterpret_cast<const float4*>(&sm.t.B[k][64 + mc * 4]);
                const float av[4] = {a.x, a.y, a.z, a.w};
                const float bv[8] = {b0.x, b0.y, b0.z, b0.w, b1.x, b1.y, b1.z, b1.w};
                #pragma unroll
                for (int r = 0; r < 4; r++)
                    #pragma unroll
                    for (int c = 0; c < 8; c++)
                        acc[r][c] = fmaf(av[r], bv[c], acc[r][c]);
            }
        }

        // Epilogue: key = y2 - 2*dot; rare insert into per-thread top-5
        #pragma unroll
        for (int c = 0; c < 8; c++) {
            int j = (c < 4) ? (mc * 4 + c) : (64 + mc * 4 + (c - 4));
            float y2v = ys[j];
            #pragma unroll
            for (int r = 0; r < 4; r++) {
                float key = fmaf(-2.f, acc[r][c], y2v);
                if (key < worst[r]) {
                    bool done = false;
                    #pragma unroll
                    for (int t = 0; t < KNN; t++)
                        if (!done && t5[r][t] == worst[r]) { t5[r][t] = key; done = true; }
                    float w = t5[r][0];
                    #pragma unroll
                    for (int t = 1; t < KNN; t++) w = fmaxf(w, t5[r][t]);
                    worst[r] = w;
                }
            }
        }
    }

    // Block-level merge: 16 mc-threads hold top-5 per query -> select 5 of 80
    __syncthreads();
    #pragma unroll
    for (int r = 0; r < 4; r++)
        #pragma unroll
        for (int t = 0; t < KNN; t++)
            sm.cand[qr * 4 + r][mc * KNN + t] = t5[r][t];
    __syncthreads();

    if (tid < QT) {
        float best[KNN], w = CUDART_INF_F;
        #pragma unroll
        for (int t = 0; t < KNN; t++) best[t] = CUDART_INF_F;
        for (int i = 0; i < 16 * KNN; i++) {
            float v = sm.cand[tid][i];
            if (v < w) {
                bool done = false;
                #pragma unroll
                for (int t = 0; t < KNN; t++)
                    if (!done && best[t] == w) { best[t] = v; done = true; }
                w = best[0];
                #pragma unroll
                for (int t = 1; t < KNN; t++) w = fmaxf(w, best[t]);
            }
        }
        size_t base = ((size_t)(q0 + tid) * NSPLIT + sp) * KNN;
        #pragma unroll
        for (int t = 0; t < KNN; t++) g_part[base + t] = best[t];
    }
}

// ---------------------------------------------------------------------------
// Kernel 3: merge splits, sqrt + normalize + mean   (thread per query)
// ---------------------------------------------------------------------------
__global__ void knn_final(const float* __restrict__ feat,
                          const float* __restrict__ minv,
                          const float* __restrict__ maxv,
                          float* __restrict__ out) {
    int q = blockIdx.x * blockDim.x + threadIdx.x;
    if (q >= NQ) return;

    const float4* p = reinterpret_cast<const float4*>(feat + (size_t)q * DIMS);
    float x2 = 0.f;
    #pragma unroll
    for (int i = 0; i < DIMS / 4; i++) {
        float4 v = p[i];
        x2 += v.x*v.x + v.y*v.y + v.z*v.z + v.w*v.w;
    }

    float best[KNN], w = CUDART_INF_F;
    #pragma unroll
    for (int t = 0; t < KNN; t++) best[t] = CUDART_INF_F;
    const float* part = g_part + (size_t)q * NSPLIT * KNN;
    for (int i = 0; i < NSPLIT * KNN; i++) {
        float v = part[i];
        if (v < w) {
            bool done = false;
            #pragma unroll
            for (int t = 0; t < KNN; t++)
                if (!done && best[t] == w) { best[t] = v; done = true; }
            w = best[0];
            #pragma unroll
            for (int t = 1; t < KNN; t++) w = fmaxf(w, best[t]);
        }
    }

    float mn = *minv, mx = *maxv;
    float inv = 1.f / (mx - mn);
    float sum = 0.f;
    #pragma unroll
    for (int t = 0; t < KNN; t++) {
        float d2 = x2 + best[t];
        float d  = sqrtf(fmaxf(d2, 0.f));
        sum += (d - mn) * inv;
    }
    out[q] = sum * (1.f / KNN);
}

// ---------------------------------------------------------------------------
extern "C" void kernel_launch(void* const* d_in, const int* in_sizes, int n_in,
                              void* d_out, int out_size) {
    const float* feat = (const float*)d_in[0];   // (2048, 128) f32
    const float* bank = (const float*)d_in[1];   // (100000, 128) f32
    const float* mnv  = (const float*)d_in[2];   // scalar f32
    const float* mxv  = (const float*)d_in[3];   // scalar f32
    // d_in[4]: n_neighbors (int scalar) — fixed K=5 for this instance

    y2_kernel<<<(MBANK + 7) / 8, 256>>>(bank);

    dim3 grid(NQ / QT, NSPLIT);
    knn_main<<<grid, NTHR>>>(feat, bank);

    knn_final<<<(NQ + 127) / 128, 128>>>(feat, mnv, mxv, (float*)d_out);
}